// round 1
// baseline (speedup 1.0000x reference)
#include <cuda_runtime.h>
#include <math.h>

#define BATCH 8
#define NPATCH 196
#define LEN_KEEP 147
#define SEQL 148
#define DM 768
#define DI 1536
#define DSTATE 16
#define DTR 48
#define XDBLN 80
#define NLAYERS 12
#define MROWS (BATCH*SEQL)   // 1184

// ---------------- scratch buffers (device globals; no allocation) ----------------
__device__ float g_patches[MROWS*DM];
__device__ int   g_rowpatch[MROWS];
__device__ int   g_ids_keep[BATCH*LEN_KEEP];
__device__ float g_h[MROWS*DM];
__device__ float g_ln[MROWS*DM];
__device__ float g_xz[MROWS*2*DI];
__device__ float g_xc[MROWS*DI];
__device__ float g_xdbl[MROWS*XDBLN];
__device__ float g_dt[MROWS*DI];
__device__ float g_y[MROWS*DI];

// ---------------- masking: ranks via O(N^2) comparison (stable argsort) ----------
__global__ void mask_kernel(const float* __restrict__ noise,
                            float* __restrict__ out_mask,
                            float* __restrict__ out_ids) {
    __shared__ float s[NPATCH];
    int b = blockIdx.x, tid = threadIdx.x;
    if (tid < NPATCH) s[tid] = noise[b*NPATCH + tid];
    __syncthreads();
    if (tid < NPATCH) {
        float v = s[tid];
        int rank = 0;
        #pragma unroll 4
        for (int j = 0; j < NPATCH; j++) {
            float u = s[j];
            rank += (u < v) || (u == v && j < tid);
        }
        out_mask[b*NPATCH + tid] = (rank >= LEN_KEEP) ? 1.0f : 0.0f;
        out_ids [b*NPATCH + tid] = (float)rank;
        if (rank < LEN_KEEP) g_ids_keep[b*LEN_KEEP + rank] = tid;
    }
}

// ---------------- gather kept patches into a dense (MROWS x 768) matrix ----------
__global__ void gather_kernel(const float* __restrict__ pix) {
    int m = blockIdx.x;
    int t = m % SEQL, b = m / SEQL;
    int tid = threadIdx.x;
    if (t == 0) {
        if (tid == 0) g_rowpatch[m] = -1;
        for (int k = tid; k < DM; k += blockDim.x) g_patches[m*DM + k] = 0.0f;
        return;
    }
    int p = g_ids_keep[b*LEN_KEEP + (t - 1)];
    if (tid == 0) g_rowpatch[m] = p;
    int pi = p / 14, pj = p % 14;
    for (int k = tid; k < DM; k += blockDim.x) {
        int c = k >> 8, rem = k & 255, r = rem >> 4, cc = rem & 15;
        g_patches[m*DM + k] =
            pix[((size_t)(b*3 + c)*224 + pi*16 + r)*224 + pj*16 + cc];
    }
}

// ---------------- generic tiled SGEMM: C = A(MxK, lda) * W(NxK)^T + epilogue -----
// EPI: 0 = plain store, 1 = patch-embed (conv_b + pos_embed / cls row),
//      2 = softplus(acc + dt_bias), 3 = residual accumulate (C += acc)
template<int BM, int BN, int BK, int TM, int TN, int EPI>
__global__ __launch_bounds__(256)
void sgemm(const float* __restrict__ A, const float* __restrict__ W,
           float* __restrict__ C, int M, int N, int K, int lda,
           const float* __restrict__ ep0, const float* __restrict__ ep1,
           const float* __restrict__ ep2, const int* __restrict__ rowinfo) {
    __shared__ float As[BK][BM + 4];
    __shared__ float Bs[BK][BN + 4];
    const int tid = threadIdx.x;
    const int m0 = blockIdx.x * BM;
    const int n0 = blockIdx.y * BN;
    constexpr int CT = BN / TN;      // threads along N
    const int tx = tid % CT;
    const int ty = tid / CT;

    float acc[TM][TN];
    #pragma unroll
    for (int i = 0; i < TM; i++)
        #pragma unroll
        for (int j = 0; j < TN; j++) acc[i][j] = 0.0f;

    constexpr int AREP = (BM * BK) / 256;
    constexpr int BREP = (BN * BK) / 256;

    for (int k0 = 0; k0 < K; k0 += BK) {
        #pragma unroll
        for (int r = 0; r < AREP; r++) {
            int idx = tid + r * 256;
            int i = idx / BK, j = idx % BK;
            int gm = m0 + i;
            As[j][i] = (gm < M) ? A[(size_t)gm * lda + k0 + j] : 0.0f;
        }
        #pragma unroll
        for (int r = 0; r < BREP; r++) {
            int idx = tid + r * 256;
            int i = idx / BK, j = idx % BK;
            Bs[j][i] = W[(size_t)(n0 + i) * K + k0 + j];
        }
        __syncthreads();
        #pragma unroll
        for (int kk = 0; kk < BK; kk++) {
            float a[TM], bb[TN];
            #pragma unroll
            for (int i = 0; i < TM; i++) a[i] = As[kk][ty*TM + i];
            #pragma unroll
            for (int j = 0; j < TN; j++) bb[j] = Bs[kk][tx*TN + j];
            #pragma unroll
            for (int i = 0; i < TM; i++)
                #pragma unroll
                for (int j = 0; j < TN; j++)
                    acc[i][j] = fmaf(a[i], bb[j], acc[i][j]);
        }
        __syncthreads();
    }

    #pragma unroll
    for (int i = 0; i < TM; i++) {
        int m = m0 + ty*TM + i;
        if (m >= M) continue;
        int rp = 0;
        if (EPI == 1) rp = rowinfo[m];
        #pragma unroll
        for (int j = 0; j < TN; j++) {
            int n = n0 + tx*TN + j;
            float v = acc[i][j];
            if (EPI == 1) {
                if (rp < 0) v = ep1[n] + ep2[n];                       // cls + pos0
                else        v = v + ep0[n] + ep2[(size_t)(1+rp)*DM + n];
            } else if (EPI == 2) {
                float x = v + ep0[n];
                v = (x > 20.0f) ? x : log1pf(__expf(x));
            }
            if (EPI == 3) C[(size_t)m * N + n] += v;
            else          C[(size_t)m * N + n]  = v;
        }
    }
}

// ---------------- depthwise causal conv1d (k=4) + SiLU ---------------------------
__global__ void conv_silu_kernel(const float* __restrict__ cw,
                                 const float* __restrict__ cb) {
    int m = blockIdx.x;
    int t = m % SEQL, b = m / SEQL;
    for (int d = threadIdx.x; d < DI; d += blockDim.x) {
        float w0 = cw[d*4+0], w1 = cw[d*4+1], w2 = cw[d*4+2], w3 = cw[d*4+3];
        float s = cb[d];
        const float* base = g_xz + (size_t)(b*SEQL) * (2*DI) + d;
        if (t >= 3) s = fmaf(w0, base[(size_t)(t-3)*(2*DI)], s);
        if (t >= 2) s = fmaf(w1, base[(size_t)(t-2)*(2*DI)], s);
        if (t >= 1) s = fmaf(w2, base[(size_t)(t-1)*(2*DI)], s);
        s = fmaf(w3, base[(size_t)t*(2*DI)], s);
        float sig = 1.0f / (1.0f + __expf(-s));
        g_xc[(size_t)m*DI + d] = s * sig;
    }
}

// ---------------- layernorm (row per block, 256 threads, DM=768) -----------------
__device__ __forceinline__ float block_reduce_sum_256(float v, float* sh, float* bc) {
    #pragma unroll
    for (int o = 16; o > 0; o >>= 1) v += __shfl_xor_sync(0xffffffffu, v, o);
    int w = threadIdx.x >> 5;
    if ((threadIdx.x & 31) == 0) sh[w] = v;
    __syncthreads();
    if (threadIdx.x == 0) {
        float s = 0.0f;
        #pragma unroll
        for (int i = 0; i < 8; i++) s += sh[i];
        *bc = s;
    }
    __syncthreads();
    return *bc;
}

__global__ void ln_kernel(const float* __restrict__ x, const float* __restrict__ w,
                          const float* __restrict__ bias, float* __restrict__ out) {
    __shared__ float sh[8];
    __shared__ float bc;
    int m = blockIdx.x, tid = threadIdx.x;
    const float* xr = x + (size_t)m * DM;
    float v0 = xr[tid], v1 = xr[tid + 256], v2 = xr[tid + 512];
    float mean = block_reduce_sum_256(v0 + v1 + v2, sh, &bc) * (1.0f / DM);
    float d0 = v0 - mean, d1 = v1 - mean, d2 = v2 - mean;
    __syncthreads();
    float var = block_reduce_sum_256(d0*d0 + d1*d1 + d2*d2, sh, &bc) * (1.0f / DM);
    float inv = rsqrtf(var + 1e-12f);
    float* o = out + (size_t)m * DM;
    o[tid]       = d0 * inv * w[tid]       + bias[tid];
    o[tid + 256] = d1 * inv * w[tid + 256] + bias[tid + 256];
    o[tid + 512] = d2 * inv * w[tid + 512] + bias[tid + 512];
}

// ---------------- selective scan: 16 lanes per channel, states in registers ------
__global__ void scan_kernel(const float* __restrict__ A_log_l,
                            const float* __restrict__ Dp_l) {
    int lane = threadIdx.x & 31;
    int warp = threadIdx.x >> 5;
    int widx = blockIdx.x * 8 + warp;
    int ch = widx * 2 + (lane >> 4);       // 2 channels per warp
    int b = ch / DI, d = ch % DI;
    int n = lane & 15;
    float Av = -__expf(A_log_l[d*DSTATE + n]);
    float Dv = Dp_l[d];
    float h = 0.0f;
    int base = b * SEQL;
    for (int t = 0; t < SEQL; t++) {
        int m = base + t;
        float dt  = g_dt[(size_t)m*DI + d];
        float xc  = g_xc[(size_t)m*DI + d];
        float Bn  = g_xdbl[(size_t)m*XDBLN + DTR + n];
        float Cn  = g_xdbl[(size_t)m*XDBLN + DTR + DSTATE + n];
        float dA  = __expf(dt * Av);
        h = fmaf(dA, h, (dt * xc) * Bn);
        float p = h * Cn;
        p += __shfl_xor_sync(0xffffffffu, p, 8);
        p += __shfl_xor_sync(0xffffffffu, p, 4);
        p += __shfl_xor_sync(0xffffffffu, p, 2);
        p += __shfl_xor_sync(0xffffffffu, p, 1);
        if (n == 0) {
            float z = g_xz[(size_t)m*(2*DI) + DI + d];
            float y = (p + xc * Dv) * (z / (1.0f + __expf(-z)));
            g_y[(size_t)m*DI + d] = y;
        }
    }
}

// ---------------- host launcher ---------------------------------------------------
extern "C" void kernel_launch(void* const* d_in, const int* in_sizes, int n_in,
                              void* d_out, int out_size) {
    const float* pixel     = (const float*)d_in[0];
    const float* noise     = (const float*)d_in[1];
    const float* conv_w    = (const float*)d_in[2];
    const float* conv_b    = (const float*)d_in[3];
    const float* cls_token = (const float*)d_in[4];
    const float* pos_embed = (const float*)d_in[5];
    const float* ln_w      = (const float*)d_in[6];
    const float* ln_b      = (const float*)d_in[7];
    const float* W_in      = (const float*)d_in[8];
    const float* conv1d_w  = (const float*)d_in[9];
    const float* conv1d_b  = (const float*)d_in[10];
    const float* W_x       = (const float*)d_in[11];
    const float* W_dt      = (const float*)d_in[12];
    const float* dt_bias   = (const float*)d_in[13];
    const float* A_log     = (const float*)d_in[14];
    const float* Dp        = (const float*)d_in[15];
    const float* W_out     = (const float*)d_in[16];
    const float* lnf_w     = (const float*)d_in[17];
    const float* lnf_b     = (const float*)d_in[18];

    float* out      = (float*)d_out;
    float* out_h    = out;                       // (8,148,768)
    float* out_mask = out + (size_t)MROWS*DM;    // (8,196)
    float* out_ids  = out_mask + BATCH*NPATCH;   // (8,196) as float

    float *p_patches, *p_h, *p_ln, *p_xz, *p_xc, *p_xdbl, *p_dt, *p_y;
    int *p_rowpatch;
    cudaGetSymbolAddress((void**)&p_patches, g_patches);
    cudaGetSymbolAddress((void**)&p_h,       g_h);
    cudaGetSymbolAddress((void**)&p_ln,      g_ln);
    cudaGetSymbolAddress((void**)&p_xz,      g_xz);
    cudaGetSymbolAddress((void**)&p_xc,      g_xc);
    cudaGetSymbolAddress((void**)&p_xdbl,    g_xdbl);
    cudaGetSymbolAddress((void**)&p_dt,      g_dt);
    cudaGetSymbolAddress((void**)&p_y,       g_y);
    cudaGetSymbolAddress((void**)&p_rowpatch, g_rowpatch);

    // masking + patch gather + patch-embed GEMM (epilogue: bias + pos embed + cls)
    mask_kernel<<<BATCH, 256>>>(noise, out_mask, out_ids);
    gather_kernel<<<MROWS, 256>>>(pixel);
    {
        dim3 g((MROWS + 127) / 128, DM / 64);
        sgemm<128,64,16,8,4,1><<<g, 256>>>(p_patches, conv_w, p_h,
            MROWS, DM, DM, DM, conv_b, cls_token, pos_embed, p_rowpatch);
    }

    for (int l = 0; l < NLAYERS; l++) {
        const float* Wi  = W_in     + (size_t)l * (2*DI) * DM;
        const float* cw  = conv1d_w + (size_t)l * DI * 4;
        const float* cb  = conv1d_b + (size_t)l * DI;
        const float* Wx  = W_x      + (size_t)l * XDBLN * DI;
        const float* Wd  = W_dt     + (size_t)l * DI * DTR;
        const float* db  = dt_bias  + (size_t)l * DI;
        const float* Al  = A_log    + (size_t)l * DI * DSTATE;
        const float* Dl  = Dp       + (size_t)l * DI;
        const float* Wo  = W_out    + (size_t)l * DM * DI;

        ln_kernel<<<MROWS, 256>>>(p_h, ln_w + l*DM, ln_b + l*DM, p_ln);

        // xz = ln @ W_in^T   (1184 x 3072, K=768)
        {
            dim3 g((MROWS + 127) / 128, (2*DI) / 64);
            sgemm<128,64,16,8,4,0><<<g, 256>>>(p_ln, Wi, p_xz,
                MROWS, 2*DI, DM, DM, nullptr, nullptr, nullptr, nullptr);
        }
        // depthwise causal conv + silu
        conv_silu_kernel<<<MROWS, 256>>>(cw, cb);
        // x_dbl = xc @ W_x^T  (1184 x 80, K=1536)
        {
            dim3 g((MROWS + 63) / 64, XDBLN / 16);
            sgemm<64,16,16,4,1,0><<<g, 256>>>(p_xc, Wx, p_xdbl,
                MROWS, XDBLN, DI, DI, nullptr, nullptr, nullptr, nullptr);
        }
        // dt = softplus(x_dbl[:, :48] @ W_dt^T + dt_bias)   (1184 x 1536, K=48, lda=80)
        {
            dim3 g((MROWS + 127) / 128, DI / 64);
            sgemm<128,64,16,8,4,2><<<g, 256>>>(p_xdbl, Wd, p_dt,
                MROWS, DI, DTR, XDBLN, db, nullptr, nullptr, nullptr);
        }
        // selective scan + D skip + gate
        scan_kernel<<<(BATCH*DI)/16, 256>>>(Al, Dl);
        // h += y @ W_out^T   (1184 x 768, K=1536)
        {
            dim3 g((MROWS + 127) / 128, DM / 64);
            sgemm<128,64,16,8,4,3><<<g, 256>>>(p_y, Wo, p_h,
                MROWS, DM, DI, DI, nullptr, nullptr, nullptr, nullptr);
        }
    }

    // final layernorm straight into the output buffer
    ln_kernel<<<MROWS, 256>>>(p_h, lnf_w, lnf_b, out_h);
}

// round 2
// speedup vs baseline: 1.1975x; 1.1975x over previous
#include <cuda_runtime.h>
#include <math.h>

#define BATCH 8
#define NPATCH 196
#define LEN_KEEP 147
#define SEQL 148
#define DM 768
#define DI 1536
#define DSTATE 16
#define DTR 48
#define XDBLN 80
#define NLAYERS 12
#define MROWS (BATCH*SEQL)   // 1184

// ---------------- scratch buffers (device globals; no allocation) ----------------
__device__ float g_patches[MROWS*DM];
__device__ int   g_rowpatch[MROWS];
__device__ int   g_ids_keep[BATCH*LEN_KEEP];
__device__ float g_h[MROWS*DM];
__device__ float g_ln[MROWS*DM];
__device__ float g_xz[MROWS*2*DI];
__device__ float g_xc[MROWS*DI];
__device__ float g_xdbl[MROWS*XDBLN];
__device__ float g_dt[MROWS*DI];
__device__ float g_y[MROWS*DI];

// ---------------- packed f32x2 helpers --------------------------------------------
__device__ __forceinline__ void ffma2(unsigned long long& acc,
                                      unsigned long long a, unsigned long long b) {
    asm("fma.rn.f32x2 %0, %1, %2, %0;" : "+l"(acc) : "l"(a), "l"(b));
}
__device__ __forceinline__ unsigned long long pack2(float x, float y) {
    unsigned long long r;
    asm("mov.b64 %0, {%1, %2};" : "=l"(r) : "f"(x), "f"(y));
    return r;
}
__device__ __forceinline__ float2 unpack2(unsigned long long v) {
    float2 f;
    asm("mov.b64 {%0, %1}, %2;" : "=f"(f.x), "=f"(f.y) : "l"(v));
    return f;
}

// ---------------- masking: ranks via O(N^2) comparison (stable argsort) ----------
__global__ void mask_kernel(const float* __restrict__ noise,
                            float* __restrict__ out_mask,
                            float* __restrict__ out_ids) {
    __shared__ float s[NPATCH];
    int b = blockIdx.x, tid = threadIdx.x;
    if (tid < NPATCH) s[tid] = noise[b*NPATCH + tid];
    __syncthreads();
    if (tid < NPATCH) {
        float v = s[tid];
        int rank = 0;
        #pragma unroll 4
        for (int j = 0; j < NPATCH; j++) {
            float u = s[j];
            rank += (u < v) || (u == v && j < tid);
        }
        out_mask[b*NPATCH + tid] = (rank >= LEN_KEEP) ? 1.0f : 0.0f;
        out_ids [b*NPATCH + tid] = (float)rank;
        if (rank < LEN_KEEP) g_ids_keep[b*LEN_KEEP + rank] = tid;
    }
}

// ---------------- gather kept patches into a dense (MROWS x 768) matrix ----------
__global__ void gather_kernel(const float* __restrict__ pix) {
    int m = blockIdx.x;
    int t = m % SEQL, b = m / SEQL;
    int tid = threadIdx.x;
    if (t == 0) {
        if (tid == 0) g_rowpatch[m] = -1;
        for (int k = tid; k < DM; k += blockDim.x) g_patches[m*DM + k] = 0.0f;
        return;
    }
    int p = g_ids_keep[b*LEN_KEEP + (t - 1)];
    if (tid == 0) g_rowpatch[m] = p;
    int pi = p / 14, pj = p % 14;
    for (int k = tid; k < DM; k += blockDim.x) {
        int c = k >> 8, rem = k & 255, r = rem >> 4, cc = rem & 15;
        g_patches[m*DM + k] =
            pix[((size_t)(b*3 + c)*224 + pi*16 + r)*224 + pj*16 + cc];
    }
}

// =============== FFMA2 double-buffered SGEMM: C = A(MxK,lda) * W(NxK)^T ===========
// EPI: 0 = plain store, 1 = patch-embed (conv_b + pos_embed / cls row),
//      2 = softplus(acc + dt_bias), 3 = residual accumulate (C += acc)
// Thread tile: TM x 8 in split-half layout (first/second half of BM and BN).
template<int BM, int BN, int TM, int EPI>
__global__ __launch_bounds__(256)
void sgemm2(const float* __restrict__ A, const float* __restrict__ W,
            float* __restrict__ C, int M, int N, int K, int lda,
            const float* __restrict__ ep0, const float* __restrict__ ep1,
            const float* __restrict__ ep2, const int* __restrict__ rowinfo) {
    constexpr int BK = 16;
    constexpr int PA = BM + 8;           // row pitch (floats); keeps 16B alignment
    constexpr int PB = BN + 8;
    constexpr int AREP = BM * BK / 256;  // floats per thread per stage
    constexpr int BREP = BN * BK / 256;
    constexpr int TMH = TM / 2;

    __shared__ __align__(16) float As[2][BK][PA];
    __shared__ __align__(16) float Bs[2][BK][PB];

    const int tid = threadIdx.x;
    const int m0 = blockIdx.x * BM;
    const int n0 = blockIdx.y * BN;
    const int tx = tid & 15;             // 16 threads along N
    const int ty = tid >> 4;             // 16 threads along M

    unsigned long long acc[TM][4];
    #pragma unroll
    for (int i = 0; i < TM; i++)
        #pragma unroll
        for (int j = 0; j < 4; j++) acc[i][j] = 0ull;

    const int KT = K / BK;

    // ---- load stage 0 ----
    #pragma unroll
    for (int r = 0; r < AREP; r++) {
        int idx = tid + r*256; int i = idx >> 4, j = idx & 15;
        int gm = m0 + i;
        As[0][j][i] = (gm < M) ? A[(size_t)gm * lda + j] : 0.0f;
    }
    #pragma unroll
    for (int r = 0; r < BREP; r++) {
        int idx = tid + r*256; int i = idx >> 4, j = idx & 15;
        Bs[0][j][i] = W[(size_t)(n0 + i) * K + j];
    }
    __syncthreads();

    int s = 0;
    for (int kt = 0; kt < KT; kt++) {
        float ra[AREP], rb[BREP];
        if (kt + 1 < KT) {
            int k0 = (kt + 1) * BK;
            #pragma unroll
            for (int r = 0; r < AREP; r++) {
                int idx = tid + r*256; int i = idx >> 4, j = idx & 15;
                int gm = m0 + i;
                ra[r] = (gm < M) ? A[(size_t)gm * lda + k0 + j] : 0.0f;
            }
            #pragma unroll
            for (int r = 0; r < BREP; r++) {
                int idx = tid + r*256; int i = idx >> 4, j = idx & 15;
                rb[r] = W[(size_t)(n0 + i) * K + k0 + j];
            }
        }
        // ---- compute over stage s ----
        #pragma unroll
        for (int kk = 0; kk < BK; kk++) {
            // a: TM floats from split halves, duplicated into packed pairs
            unsigned long long ap[TM];
            if (TM == 8) {
                float4 a0 = *(const float4*)&As[s][kk][ty*4];
                float4 a1 = *(const float4*)&As[s][kk][BM/2 + ty*4];
                ap[0]=pack2(a0.x,a0.x); ap[1]=pack2(a0.y,a0.y);
                ap[2]=pack2(a0.z,a0.z); ap[3]=pack2(a0.w,a0.w);
                ap[4]=pack2(a1.x,a1.x); ap[5]=pack2(a1.y,a1.y);
                ap[6]=pack2(a1.z,a1.z); ap[7]=pack2(a1.w,a1.w);
            } else {
                float2 a0 = *(const float2*)&As[s][kk][ty*2];
                float2 a1 = *(const float2*)&As[s][kk][BM/2 + ty*2];
                ap[0]=pack2(a0.x,a0.x); ap[1]=pack2(a0.y,a0.y);
                ap[2]=pack2(a1.x,a1.x); ap[3]=pack2(a1.y,a1.y);
            }
            // b: 8 floats = 4 packed pairs, read directly as u64 pairs
            ulonglong2 b0 = *(const ulonglong2*)&Bs[s][kk][tx*4];
            ulonglong2 b1 = *(const ulonglong2*)&Bs[s][kk][BN/2 + tx*4];
            unsigned long long bp[4] = {b0.x, b0.y, b1.x, b1.y};
            #pragma unroll
            for (int i = 0; i < TM; i++)
                #pragma unroll
                for (int j = 0; j < 4; j++)
                    ffma2(acc[i][j], ap[i], bp[j]);
        }
        if (kt + 1 < KT) {
            int sn = s ^ 1;
            #pragma unroll
            for (int r = 0; r < AREP; r++) {
                int idx = tid + r*256; int i = idx >> 4, j = idx & 15;
                As[sn][j][i] = ra[r];
            }
            #pragma unroll
            for (int r = 0; r < BREP; r++) {
                int idx = tid + r*256; int i = idx >> 4, j = idx & 15;
                Bs[sn][j][i] = rb[r];
            }
            __syncthreads();
            s = sn;
        }
    }

    // ---- epilogue ----
    #pragma unroll
    for (int i = 0; i < TM; i++) {
        int m = m0 + ((i < TMH) ? (ty*TMH + i) : (BM/2 + ty*TMH + (i - TMH)));
        if (m >= M) continue;
        int rp = 0;
        if (EPI == 1) rp = rowinfo[m];
        #pragma unroll
        for (int j = 0; j < 4; j++) {
            float2 v2 = unpack2(acc[i][j]);
            int nbase = n0 + ((j < 2) ? (tx*4 + j*2) : (BN/2 + tx*4 + (j-2)*2));
            float vv[2] = {v2.x, v2.y};
            #pragma unroll
            for (int q = 0; q < 2; q++) {
                int n = nbase + q;
                float v = vv[q];
                if (EPI == 1) {
                    if (rp < 0) v = ep1[n] + ep2[n];
                    else        v = v + ep0[n] + ep2[(size_t)(1+rp)*DM + n];
                } else if (EPI == 2) {
                    float x = v + ep0[n];
                    v = (x > 20.0f) ? x : log1pf(__expf(x));
                }
                if (EPI == 3) C[(size_t)m * N + n] += v;
                else          C[(size_t)m * N + n]  = v;
            }
        }
    }
}

// ---------------- small SGEMM for x_dbl (N=80) ------------------------------------
template<int BM, int BN, int BK, int TM, int TN>
__global__ __launch_bounds__(256)
void sgemm_small(const float* __restrict__ A, const float* __restrict__ W,
                 float* __restrict__ C, int M, int N, int K, int lda) {
    __shared__ float As[BK][BM + 4];
    __shared__ float Bs[BK][BN + 4];
    const int tid = threadIdx.x;
    const int m0 = blockIdx.x * BM;
    const int n0 = blockIdx.y * BN;
    constexpr int CT = BN / TN;
    const int tx = tid % CT;
    const int ty = tid / CT;
    float acc[TM][TN];
    #pragma unroll
    for (int i = 0; i < TM; i++)
        #pragma unroll
        for (int j = 0; j < TN; j++) acc[i][j] = 0.0f;
    constexpr int AREP = (BM * BK) / 256;
    constexpr int BREP = (BN * BK) / 256;
    for (int k0 = 0; k0 < K; k0 += BK) {
        #pragma unroll
        for (int r = 0; r < AREP; r++) {
            int idx = tid + r * 256;
            int i = idx / BK, j = idx % BK;
            int gm = m0 + i;
            As[j][i] = (gm < M) ? A[(size_t)gm * lda + k0 + j] : 0.0f;
        }
        #pragma unroll
        for (int r = 0; r < BREP; r++) {
            int idx = tid + r * 256;
            int i = idx / BK, j = idx % BK;
            Bs[j][i] = W[(size_t)(n0 + i) * K + k0 + j];
        }
        __syncthreads();
        #pragma unroll
        for (int kk = 0; kk < BK; kk++) {
            float a[TM], bb[TN];
            #pragma unroll
            for (int i = 0; i < TM; i++) a[i] = As[kk][ty*TM + i];
            #pragma unroll
            for (int j = 0; j < TN; j++) bb[j] = Bs[kk][tx*TN + j];
            #pragma unroll
            for (int i = 0; i < TM; i++)
                #pragma unroll
                for (int j = 0; j < TN; j++)
                    acc[i][j] = fmaf(a[i], bb[j], acc[i][j]);
        }
        __syncthreads();
    }
    #pragma unroll
    for (int i = 0; i < TM; i++) {
        int m = m0 + ty*TM + i;
        if (m >= M) continue;
        #pragma unroll
        for (int j = 0; j < TN; j++) {
            int n = n0 + tx*TN + j;
            C[(size_t)m * N + n] = acc[i][j];
        }
    }
}

// ---------------- depthwise causal conv1d (k=4) + SiLU ---------------------------
__global__ void conv_silu_kernel(const float* __restrict__ cw,
                                 const float* __restrict__ cb) {
    int m = blockIdx.x;
    int t = m % SEQL, b = m / SEQL;
    for (int d = threadIdx.x; d < DI; d += blockDim.x) {
        float w0 = cw[d*4+0], w1 = cw[d*4+1], w2 = cw[d*4+2], w3 = cw[d*4+3];
        float s = cb[d];
        const float* base = g_xz + (size_t)(b*SEQL) * (2*DI) + d;
        if (t >= 3) s = fmaf(w0, base[(size_t)(t-3)*(2*DI)], s);
        if (t >= 2) s = fmaf(w1, base[(size_t)(t-2)*(2*DI)], s);
        if (t >= 1) s = fmaf(w2, base[(size_t)(t-1)*(2*DI)], s);
        s = fmaf(w3, base[(size_t)t*(2*DI)], s);
        float sig = 1.0f / (1.0f + __expf(-s));
        g_xc[(size_t)m*DI + d] = s * sig;
    }
}

// ---------------- layernorm (row per block, 256 threads, DM=768) -----------------
__device__ __forceinline__ float block_reduce_sum_256(float v, float* sh, float* bc) {
    #pragma unroll
    for (int o = 16; o > 0; o >>= 1) v += __shfl_xor_sync(0xffffffffu, v, o);
    int w = threadIdx.x >> 5;
    if ((threadIdx.x & 31) == 0) sh[w] = v;
    __syncthreads();
    if (threadIdx.x == 0) {
        float s = 0.0f;
        #pragma unroll
        for (int i = 0; i < 8; i++) s += sh[i];
        *bc = s;
    }
    __syncthreads();
    return *bc;
}

__global__ void ln_kernel(const float* __restrict__ x, const float* __restrict__ w,
                          const float* __restrict__ bias, float* __restrict__ out) {
    __shared__ float sh[8];
    __shared__ float bc;
    int m = blockIdx.x, tid = threadIdx.x;
    const float* xr = x + (size_t)m * DM;
    float v0 = xr[tid], v1 = xr[tid + 256], v2 = xr[tid + 512];
    float mean = block_reduce_sum_256(v0 + v1 + v2, sh, &bc) * (1.0f / DM);
    float d0 = v0 - mean, d1 = v1 - mean, d2 = v2 - mean;
    __syncthreads();
    float var = block_reduce_sum_256(d0*d0 + d1*d1 + d2*d2, sh, &bc) * (1.0f / DM);
    float inv = rsqrtf(var + 1e-12f);
    float* o = out + (size_t)m * DM;
    o[tid]       = d0 * inv * w[tid]       + bias[tid];
    o[tid + 256] = d1 * inv * w[tid + 256] + bias[tid + 256];
    o[tid + 512] = d2 * inv * w[tid + 512] + bias[tid + 512];
}

// ---------------- selective scan: 16 lanes per channel, states in registers ------
__global__ void scan_kernel(const float* __restrict__ A_log_l,
                            const float* __restrict__ Dp_l) {
    int lane = threadIdx.x & 31;
    int warp = threadIdx.x >> 5;
    int widx = blockIdx.x * 8 + warp;
    int ch = widx * 2 + (lane >> 4);       // 2 channels per warp
    int b = ch / DI, d = ch % DI;
    int n = lane & 15;
    float Av = -__expf(A_log_l[d*DSTATE + n]);
    float Dv = Dp_l[d];
    float h = 0.0f;
    int base = b * SEQL;
    for (int t = 0; t < SEQL; t++) {
        int m = base + t;
        float dt  = g_dt[(size_t)m*DI + d];
        float xc  = g_xc[(size_t)m*DI + d];
        float Bn  = g_xdbl[(size_t)m*XDBLN + DTR + n];
        float Cn  = g_xdbl[(size_t)m*XDBLN + DTR + DSTATE + n];
        float dA  = __expf(dt * Av);
        h = fmaf(dA, h, (dt * xc) * Bn);
        float p = h * Cn;
        p += __shfl_xor_sync(0xffffffffu, p, 8);
        p += __shfl_xor_sync(0xffffffffu, p, 4);
        p += __shfl_xor_sync(0xffffffffu, p, 2);
        p += __shfl_xor_sync(0xffffffffu, p, 1);
        if (n == 0) {
            float z = g_xz[(size_t)m*(2*DI) + DI + d];
            float y = (p + xc * Dv) * (z / (1.0f + __expf(-z)));
            g_y[(size_t)m*DI + d] = y;
        }
    }
}

// ---------------- host launcher ---------------------------------------------------
extern "C" void kernel_launch(void* const* d_in, const int* in_sizes, int n_in,
                              void* d_out, int out_size) {
    const float* pixel     = (const float*)d_in[0];
    const float* noise     = (const float*)d_in[1];
    const float* conv_w    = (const float*)d_in[2];
    const float* conv_b    = (const float*)d_in[3];
    const float* cls_token = (const float*)d_in[4];
    const float* pos_embed = (const float*)d_in[5];
    const float* ln_w      = (const float*)d_in[6];
    const float* ln_b      = (const float*)d_in[7];
    const float* W_in      = (const float*)d_in[8];
    const float* conv1d_w  = (const float*)d_in[9];
    const float* conv1d_b  = (const float*)d_in[10];
    const float* W_x       = (const float*)d_in[11];
    const float* W_dt      = (const float*)d_in[12];
    const float* dt_bias   = (const float*)d_in[13];
    const float* A_log     = (const float*)d_in[14];
    const float* Dp        = (const float*)d_in[15];
    const float* W_out     = (const float*)d_in[16];
    const float* lnf_w     = (const float*)d_in[17];
    const float* lnf_b     = (const float*)d_in[18];

    float* out      = (float*)d_out;
    float* out_h    = out;                       // (8,148,768)
    float* out_mask = out + (size_t)MROWS*DM;    // (8,196)
    float* out_ids  = out_mask + BATCH*NPATCH;   // (8,196) as float

    float *p_patches, *p_h, *p_ln, *p_xz, *p_xc, *p_xdbl, *p_dt, *p_y;
    int *p_rowpatch;
    cudaGetSymbolAddress((void**)&p_patches, g_patches);
    cudaGetSymbolAddress((void**)&p_h,       g_h);
    cudaGetSymbolAddress((void**)&p_ln,      g_ln);
    cudaGetSymbolAddress((void**)&p_xz,      g_xz);
    cudaGetSymbolAddress((void**)&p_xc,      g_xc);
    cudaGetSymbolAddress((void**)&p_xdbl,    g_xdbl);
    cudaGetSymbolAddress((void**)&p_dt,      g_dt);
    cudaGetSymbolAddress((void**)&p_y,       g_y);
    cudaGetSymbolAddress((void**)&p_rowpatch, g_rowpatch);

    // masking + patch gather + patch-embed GEMM (epilogue: bias + pos embed + cls)
    mask_kernel<<<BATCH, 256>>>(noise, out_mask, out_ids);
    gather_kernel<<<MROWS, 256>>>(pixel);
    {
        dim3 g((MROWS + 63) / 64, DM / 128);
        sgemm2<64,128,4,1><<<g, 256>>>(p_patches, conv_w, p_h,
            MROWS, DM, DM, DM, conv_b, cls_token, pos_embed, p_rowpatch);
    }

    for (int l = 0; l < NLAYERS; l++) {
        const float* Wi  = W_in     + (size_t)l * (2*DI) * DM;
        const float* cw  = conv1d_w + (size_t)l * DI * 4;
        const float* cb  = conv1d_b + (size_t)l * DI;
        const float* Wx  = W_x      + (size_t)l * XDBLN * DI;
        const float* Wd  = W_dt     + (size_t)l * DI * DTR;
        const float* db  = dt_bias  + (size_t)l * DI;
        const float* Al  = A_log    + (size_t)l * DI * DSTATE;
        const float* Dl  = Dp       + (size_t)l * DI;
        const float* Wo  = W_out    + (size_t)l * DM * DI;

        ln_kernel<<<MROWS, 256>>>(p_h, ln_w + l*DM, ln_b + l*DM, p_ln);

        // xz = ln @ W_in^T   (1184 x 3072, K=768)
        {
            dim3 g((MROWS + 127) / 128, (2*DI) / 128);
            sgemm2<128,128,8,0><<<g, 256>>>(p_ln, Wi, p_xz,
                MROWS, 2*DI, DM, DM, nullptr, nullptr, nullptr, nullptr);
        }
        // depthwise causal conv + silu
        conv_silu_kernel<<<MROWS, 256>>>(cw, cb);
        // x_dbl = xc @ W_x^T  (1184 x 80, K=1536)
        {
            dim3 g((MROWS + 63) / 64, XDBLN / 16);
            sgemm_small<64,16,16,4,1><<<g, 256>>>(p_xc, Wx, p_xdbl,
                MROWS, XDBLN, DI, DI);
        }
        // dt = softplus(x_dbl[:, :48] @ W_dt^T + dt_bias)   (1184 x 1536, K=48, lda=80)
        {
            dim3 g((MROWS + 127) / 128, DI / 128);
            sgemm2<128,128,8,2><<<g, 256>>>(p_xdbl, Wd, p_dt,
                MROWS, DI, DTR, XDBLN, db, nullptr, nullptr, nullptr);
        }
        // selective scan + D skip + gate
        scan_kernel<<<(BATCH*DI)/16, 256>>>(Al, Dl);
        // h += y @ W_out^T   (1184 x 768, K=1536)
        {
            dim3 g((MROWS + 63) / 64, DM / 128);
            sgemm2<64,128,4,3><<<g, 256>>>(p_y, Wo, p_h,
                MROWS, DM, DI, DI, nullptr, nullptr, nullptr, nullptr);
        }
    }

    // final layernorm straight into the output buffer
    ln_kernel<<<MROWS, 256>>>(p_h, lnf_w, lnf_b, out_h);
}